// round 11
// baseline (speedup 1.0000x reference)
#include <cuda_runtime.h>
#include <cstdint>

// Problem dims
#define BATCH 8192
#define INF   784
#define HID   4096
#define OUTF  10

// int8 2-limb layout: x = a/16 + b/4064 + eps, |eps| <= 1/8128
// limb a: bytes [0,800), limb b: [800,1600), zero pad [1600,1664)
#define KSB   800            // S (weight) row bytes (50 x 16B)
#define KXB   1664           // X row bytes = 13 chunks * 128
#define NCH   13             // K chunks of 128B (52 k32-steps; steps 50,51 are zero pad -> skipped)
// limb boundary: before k32-step 25 -> (j==6, kk==1): acc *= 254  (4064/16)

// GEMM1 tiling: CTA 128x64, 4 warps as 2(M) x 2(N), warp tile 64x32, BK=128 int8
#define BM 128
#define BN 64
#define STAGES 3
#define A_BYTES (BM * 128)   // 16384
#define B_BYTES (BN * 128)   // 8192
#define STAGE_BYTES (A_BYTES + B_BYTES)          // 24576
#define SMEM_TOTAL  (STAGES * STAGE_BYTES)       // 73728 -> 3 CTAs/SM (216KB smem, ~54K regs)

// epilogue h smem: 128 rows x 68 floats (row stride 272B -> conflict-free float4 reads)
#define HS 68

// -------------------- scratch (allowed: __device__ globals) --------------------
__device__ __align__(128) signed char g_Xq[(size_t)BATCH * KXB];
__device__ __align__(128) signed char g_Sq[(size_t)HID * KSB + 1024];  // +pad for wrap overread

// -------------------- PTX helpers (compute_100 baseline only) --------------------
__device__ __forceinline__ uint32_t smem_u32(const void* p) {
    uint32_t a;
    asm("{ .reg .u64 t; cvta.to.shared.u64 t, %1; cvt.u32.u64 %0, t; }" : "=r"(a) : "l"(p));
    return a;
}
__device__ __forceinline__ uint32_t swz128(uint32_t off) {
    return off ^ ((off >> 3) & 0x70u);
}
__device__ __forceinline__ void cp16(uint32_t dst, const void* src) {
    asm volatile("cp.async.cg.shared.global [%0], [%1], 16;\n" :: "r"(dst), "l"(src));
}
__device__ __forceinline__ void cp_commit() {
    asm volatile("cp.async.commit_group;\n" ::: "memory");
}
__device__ __forceinline__ void ldsm_x4(uint32_t& r0, uint32_t& r1, uint32_t& r2, uint32_t& r3,
                                        uint32_t addr) {
    asm volatile("ldmatrix.sync.aligned.m8n8.x4.shared.b16 {%0,%1,%2,%3}, [%4];"
                 : "=r"(r0), "=r"(r1), "=r"(r2), "=r"(r3) : "r"(addr));
}
__device__ __forceinline__ void imma16832(int* c, uint32_t a0, uint32_t a1, uint32_t a2,
                                          uint32_t a3, uint32_t b0, uint32_t b1) {
    asm volatile("mma.sync.aligned.m16n8k32.row.col.s32.s8.s8.s32 "
                 "{%0,%1,%2,%3}, {%4,%5,%6,%7}, {%8,%9}, {%0,%1,%2,%3};"
                 : "+r"(c[0]), "+r"(c[1]), "+r"(c[2]), "+r"(c[3])
                 : "r"(a0), "r"(a1), "r"(a2), "r"(a3), "r"(b0), "r"(b1));
}

// -------------------- prep kernels (vectorized) --------------------
__global__ void prep_x_kernel(const float* __restrict__ x) {
    int idx = blockIdx.x * blockDim.x + threadIdx.x;
    if (idx >= BATCH * 216) return;
    int row = idx / 216;
    int kg  = idx - row * 216;
    if (kg >= 200) {   // tail bytes [1600, 1664)
        *(uchar4*)(g_Xq + (size_t)row * KXB + 1600 + (kg - 200) * 4) = make_uchar4(0, 0, 0, 0);
        return;
    }
    uchar4 la, lb;
    if (kg < INF / 4) {
        float4 f4 = *(const float4*)(x + (size_t)row * INF + kg * 4);
        float fs[4] = {f4.x, f4.y, f4.z, f4.w};
        unsigned char va[4], vb[4];
#pragma unroll
        for (int i = 0; i < 4; i++) {
            float f = fs[i];
            float a = rintf(f * 16.0f);
            float r1 = fmaf(a, -0.0625f, f);
            float b = rintf(r1 * 4064.0f);
            va[i] = (unsigned char)(signed char)(int)a;
            vb[i] = (unsigned char)(signed char)(int)b;
        }
        la = make_uchar4(va[0], va[1], va[2], va[3]);
        lb = make_uchar4(vb[0], vb[1], vb[2], vb[3]);
    } else {
        la = lb = make_uchar4(0, 0, 0, 0);
    }
    size_t base = (size_t)row * KXB + kg * 4;
    *(uchar4*)(g_Xq + base)        = la;
    *(uchar4*)(g_Xq + base + 800)  = lb;
}

__global__ void prep_w_kernel(const float* __restrict__ W1) {
    int idx = blockIdx.x * blockDim.x + threadIdx.x;
    if (idx >= HID * 200) return;
    int row = idx / 200;
    int kg  = idx - row * 200;
    uchar4 v = make_uchar4(0, 0, 0, 0);
    if (kg < INF / 4) {
        float4 w4 = *(const float4*)(W1 + (size_t)row * INF + kg * 4);
        float ws[4] = {w4.x, w4.y, w4.z, w4.w};
        unsigned char s[4];
#pragma unroll
        for (int i = 0; i < 4; i++) {
            float w = ws[i];
            s[i] = (unsigned char)(signed char)((w > 0.0f) ? 1 : ((w < 0.0f) ? -1 : 0));
        }
        v = make_uchar4(s[0], s[1], s[2], s[3]);
    }
    *(uchar4*)(g_Sq + (size_t)row * KSB + kg * 4) = v;
}

__global__ void init_out_kernel(const float* __restrict__ b2, float* __restrict__ out) {
    int i = blockIdx.x * blockDim.x + threadIdx.x;
    if (i < BATCH * OUTF) out[i] = b2[i % OUTF];
}

// -------------------- GEMM1 + fused FC2 --------------------
__device__ __forceinline__ void load_chunk(uint32_t sbase, int stage, int kc,
                                           int m0, int n0, int tid) {
    uint32_t sa = sbase + stage * STAGE_BYTES;
    uint32_t sb = sa + A_BYTES;
    const signed char* gA = g_Xq + (size_t)m0 * KXB + (size_t)kc * 128;
#pragma unroll
    for (int i = 0; i < 8; i++) {                 // A: 128 rows x 8 x 16B, 128 threads
        int id = i * 128 + tid;
        int r = id >> 3, s = id & 7;
        cp16(sa + swz128((uint32_t)(r * 128 + s * 16)), gA + (size_t)r * KXB + s * 16);
    }
#pragma unroll
    for (int i = 0; i < 4; i++) {                 // B: 64 rows; source wraps mod 800 per 16B
        int id = i * 128 + tid;
        int r = id >> 3, s = id & 7;
        int g = kc * 128 + s * 16;
        int bsrc = (g >= 1600) ? (g - 1600) : ((g >= 800) ? (g - 800) : g);
        cp16(sb + swz128((uint32_t)(r * 128 + s * 16)),
             g_Sq + (size_t)(n0 + r) * KSB + bsrc);
    }
}

__global__ void __launch_bounds__(128, 3) gemm1_kernel(const float* __restrict__ b1,
                                                       const float* __restrict__ W2,
                                                       float* __restrict__ out) {
    extern __shared__ char dsm[];
    const int tid  = threadIdx.x;
    const int lane = tid & 31;
    const int wid  = tid >> 5;
    const int wm   = wid & 1;        // M offset wm*64
    const int wn   = (wid >> 1) & 1; // N offset wn*32
    const int m0 = blockIdx.x * BM;
    const int n0 = blockIdx.y * BN;
    const uint32_t sbase = smem_u32(dsm);

    // per-thread ldmatrix base byte offsets (pre-swizzle); same formulas as validated R7/R10
    const uint32_t aoff0 = (uint32_t)((wm * 64 + (lane & 15)) * 128 + (lane >> 4) * 16);
    const uint32_t boff0 = (uint32_t)((wn * 32 + (lane & 7) + ((lane >> 4) << 3)) * 128
                                      + ((lane >> 3) & 1) * 16);

    int acc[4][4][4];
#pragma unroll
    for (int mf = 0; mf < 4; mf++)
#pragma unroll
        for (int nf = 0; nf < 4; nf++)
#pragma unroll
            for (int i = 0; i < 4; i++) acc[mf][nf][i] = 0;

    // prologue
    load_chunk(sbase, 0, 0, m0, n0, tid); cp_commit();
    load_chunk(sbase, 1, 1, m0, n0, tid); cp_commit();

    int stage = 0;
    for (int j = 0; j < NCH; j++) {
        asm volatile("cp.async.wait_group 1;\n" ::: "memory");
        __syncthreads();

        uint32_t sa = sbase + stage * STAGE_BYTES;
        uint32_t sb = sa + A_BYTES;
        uint32_t af[2][4][4];
        uint32_t bf[2][4][2];
        // preload kk=0 fragments FIRST (ldsm latency overlaps cp.async issue below)
#pragma unroll
        for (int mf = 0; mf < 4; mf++)
            ldsm_x4(af[0][mf][0], af[0][mf][1], af[0][mf][2], af[0][mf][3],
                    sa + swz128(aoff0 + (uint32_t)(mf * 2048)));
        {
            uint32_t r0, r1, r2, r3;
            ldsm_x4(r0, r1, r2, r3, sb + swz128(boff0));
            bf[0][0][0] = r0;  bf[0][0][1] = r1;
            bf[0][1][0] = r2;  bf[0][1][1] = r3;
            ldsm_x4(r0, r1, r2, r3, sb + swz128(boff0 + 2048u));
            bf[0][2][0] = r0;  bf[0][2][1] = r1;
            bf[0][3][0] = r2;  bf[0][3][1] = r3;
        }

        int jn = j + 2;
        if (jn < NCH) {
            int sn = stage + 2; if (sn >= STAGES) sn -= STAGES;
            load_chunk(sbase, sn, jn, m0, n0, tid);
        }
        cp_commit();

#pragma unroll
        for (int kk = 0; kk < 4; kk++) {
            const int cur = kk & 1, nxt = cur ^ 1;
            if (j == 12 && kk >= 2) break;   // steps 50,51 are zero pad: exact skip
            // limb boundary before k32-step 25: acc *= 254 (= 4064/16, exact in s32)
            if (kk == 1 && j == 6) {
#pragma unroll
                for (int mf = 0; mf < 4; mf++)
#pragma unroll
                    for (int nf = 0; nf < 4; nf++)
#pragma unroll
                        for (int i = 0; i < 4; i++) acc[mf][nf][i] *= 254;
            }
            if (kk < 3 && !(j == 12 && kk == 1)) {   // prefetch kk+1 frags while issuing IMMAs
#pragma unroll
                for (int mf = 0; mf < 4; mf++)
                    ldsm_x4(af[nxt][mf][0], af[nxt][mf][1], af[nxt][mf][2], af[nxt][mf][3],
                            sa + swz128(aoff0 + (uint32_t)(mf * 2048 + (kk + 1) * 32)));
                uint32_t r0, r1, r2, r3;
                ldsm_x4(r0, r1, r2, r3, sb + swz128(boff0 + (uint32_t)((kk + 1) * 32)));
                bf[nxt][0][0] = r0;  bf[nxt][0][1] = r1;
                bf[nxt][1][0] = r2;  bf[nxt][1][1] = r3;
                ldsm_x4(r0, r1, r2, r3, sb + swz128(boff0 + (uint32_t)(2048 + (kk + 1) * 32)));
                bf[nxt][2][0] = r0;  bf[nxt][2][1] = r1;
                bf[nxt][3][0] = r2;  bf[nxt][3][1] = r3;
            }
#pragma unroll
            for (int mf = 0; mf < 4; mf++)
#pragma unroll
                for (int nf = 0; nf < 4; nf++)
                    imma16832(acc[mf][nf], af[cur][mf][0], af[cur][mf][1],
                              af[cur][mf][2], af[cur][mf][3],
                              bf[cur][nf][0], bf[cur][nf][1]);
        }
        stage++; if (stage >= STAGES) stage = 0;
    }

    // ---- epilogue: h tile -> smem (clip(acc/4064 + b1)), then fused fc2 partial ----
    __syncthreads();   // everyone done reading stage smem before overwrite
    float* hs = (float*)dsm;
    const float SCL = (float)(1.0 / 4064.0);
    const int rloc0 = wm * 64 + (lane >> 2);
    const int cloc0 = wn * 32 + (lane & 3) * 2;
#pragma unroll
    for (int mf = 0; mf < 4; mf++) {
#pragma unroll
        for (int nf = 0; nf < 4; nf++) {
            int cl = cloc0 + nf * 8;
            float bb0 = __ldg(b1 + n0 + cl), bb1 = __ldg(b1 + n0 + cl + 1);
#pragma unroll
            for (int half = 0; half < 2; half++) {
                int rl = rloc0 + mf * 16 + half * 8;
                float v0 = fmaf((float)acc[mf][nf][2 * half],     SCL, bb0);
                float v1 = fmaf((float)acc[mf][nf][2 * half + 1], SCL, bb1);
                v0 = fminf(1.0f, fmaxf(-1.0f, v0));
                v1 = fminf(1.0f, fmaxf(-1.0f, v1));
                *(float2*)(hs + rl * HS + cl) = make_float2(v0, v1);
            }
        }
    }
    __syncthreads();

    // fc2 partial: thread t owns row t, 64 cols; W2 loads warp-uniform (L1-resident)
    {
        float accf[OUTF];
#pragma unroll
        for (int o = 0; o < OUTF; o++) accf[o] = 0.0f;
        const float4* hv4 = (const float4*)(hs + tid * HS);
        const float4* W2v = (const float4*)W2;
        const int base = n0 >> 2;
#pragma unroll 4
        for (int c4 = 0; c4 < 16; c4++) {
            float4 h4 = hv4[c4];
#pragma unroll
            for (int o = 0; o < OUTF; o++) {
                float4 w = __ldg(&W2v[o * (HID / 4) + base + c4]);
                accf[o] += h4.x * w.x + h4.y * w.y + h4.z * w.z + h4.w * w.w;
            }
        }
        float* op = out + (size_t)(m0 + tid) * OUTF;
#pragma unroll
        for (int o = 0; o < OUTF; o++) atomicAdd(op + o, accf[o]);
    }
}

// -------------------- launch --------------------
extern "C" void kernel_launch(void* const* d_in, const int* in_sizes, int n_in,
                              void* d_out, int out_size) {
    const float* x  = (const float*)d_in[0];
    const float* W1 = (const float*)d_in[1];
    const float* b1 = (const float*)d_in[2];
    const float* W2 = (const float*)d_in[3];
    const float* b2 = (const float*)d_in[4];
    float* out = (float*)d_out;

    cudaFuncSetAttribute(gemm1_kernel, cudaFuncAttributeMaxDynamicSharedMemorySize, SMEM_TOTAL);

    init_out_kernel<<<(BATCH * OUTF + 255) / 256, 256>>>(b2, out);
    prep_x_kernel<<<(BATCH * 216 + 255) / 256, 256>>>(x);
    prep_w_kernel<<<(HID * 200 + 255) / 256, 256>>>(W1);
    gemm1_kernel<<<dim3(BATCH / BM, HID / BN), 128, SMEM_TOTAL>>>(b1, W2, out);
}

// round 12
// speedup vs baseline: 1.0035x; 1.0035x over previous
#include <cuda_runtime.h>
#include <cstdint>

// Problem dims
#define BATCH 8192
#define INF   784
#define HID   4096
#define OUTF  10

// int8 2-limb layout: x = a/16 + b/4064 + eps, |eps| <= 1/8128
// limb a: bytes [0,800), limb b: [800,1600), zero pad [1600,1664)
#define KSB   800            // S (weight) row bytes (50 x 16B)
#define KXB   1664           // X row bytes = 13 chunks * 128
#define NCH   13             // K chunks of 128B (52 k32-steps; steps 50,51 are zero pad -> skipped)
// limb boundary: before k32-step 25 -> (j==6, kk==1): acc *= 254  (4064/16)

// GEMM1 tiling: CTA 128x64, 4 warps as 2(M) x 2(N), warp tile 64x32, BK=128 int8
#define BM 128
#define BN 64
#define STAGES 3
#define A_BYTES (BM * 128)   // 16384
#define B_BYTES (BN * 128)   // 8192
#define STAGE_BYTES (A_BYTES + B_BYTES)          // 24576
#define SMEM_TOTAL  (STAGES * STAGE_BYTES)       // 73728 -> 3 CTAs/SM (216KB smem, ~54K regs)

// epilogue h smem: 128 rows x 68 floats (row stride 272B -> conflict-free float4 reads)
#define HS 68

// -------------------- scratch (allowed: __device__ globals) --------------------
__device__ __align__(128) signed char g_Xq[(size_t)BATCH * KXB];
__device__ __align__(128) signed char g_Sq[(size_t)HID * KSB + 1024];  // +pad for wrap overread

// -------------------- PTX helpers (compute_100 baseline only) --------------------
__device__ __forceinline__ uint32_t smem_u32(const void* p) {
    uint32_t a;
    asm("{ .reg .u64 t; cvta.to.shared.u64 t, %1; cvt.u32.u64 %0, t; }" : "=r"(a) : "l"(p));
    return a;
}
__device__ __forceinline__ uint32_t swz128(uint32_t off) {
    return off ^ ((off >> 3) & 0x70u);
}
__device__ __forceinline__ void cp16(uint32_t dst, const void* src) {
    asm volatile("cp.async.cg.shared.global [%0], [%1], 16;\n" :: "r"(dst), "l"(src));
}
__device__ __forceinline__ void cp_commit() {
    asm volatile("cp.async.commit_group;\n" ::: "memory");
}
__device__ __forceinline__ void ldsm_x4(uint32_t& r0, uint32_t& r1, uint32_t& r2, uint32_t& r3,
                                        uint32_t addr) {
    asm volatile("ldmatrix.sync.aligned.m8n8.x4.shared.b16 {%0,%1,%2,%3}, [%4];"
                 : "=r"(r0), "=r"(r1), "=r"(r2), "=r"(r3) : "r"(addr));
}
__device__ __forceinline__ void imma16832(int* c, uint32_t a0, uint32_t a1, uint32_t a2,
                                          uint32_t a3, uint32_t b0, uint32_t b1) {
    asm volatile("mma.sync.aligned.m16n8k32.row.col.s32.s8.s8.s32 "
                 "{%0,%1,%2,%3}, {%4,%5,%6,%7}, {%8,%9}, {%0,%1,%2,%3};"
                 : "+r"(c[0]), "+r"(c[1]), "+r"(c[2]), "+r"(c[3])
                 : "r"(a0), "r"(a1), "r"(a2), "r"(a3), "r"(b0), "r"(b1));
}

// -------------------- prep kernels (vectorized) --------------------
__global__ void prep_x_kernel(const float* __restrict__ x) {
    int idx = blockIdx.x * blockDim.x + threadIdx.x;
    if (idx >= BATCH * 216) return;
    int row = idx / 216;
    int kg  = idx - row * 216;
    if (kg >= 200) {   // tail bytes [1600, 1664)
        *(uchar4*)(g_Xq + (size_t)row * KXB + 1600 + (kg - 200) * 4) = make_uchar4(0, 0, 0, 0);
        return;
    }
    uchar4 la, lb;
    if (kg < INF / 4) {
        float4 f4 = *(const float4*)(x + (size_t)row * INF + kg * 4);
        float fs[4] = {f4.x, f4.y, f4.z, f4.w};
        unsigned char va[4], vb[4];
#pragma unroll
        for (int i = 0; i < 4; i++) {
            float f = fs[i];
            float a = rintf(f * 16.0f);
            float r1 = fmaf(a, -0.0625f, f);
            float b = rintf(r1 * 4064.0f);
            va[i] = (unsigned char)(signed char)(int)a;
            vb[i] = (unsigned char)(signed char)(int)b;
        }
        la = make_uchar4(va[0], va[1], va[2], va[3]);
        lb = make_uchar4(vb[0], vb[1], vb[2], vb[3]);
    } else {
        la = lb = make_uchar4(0, 0, 0, 0);
    }
    size_t base = (size_t)row * KXB + kg * 4;
    *(uchar4*)(g_Xq + base)        = la;
    *(uchar4*)(g_Xq + base + 800)  = lb;
}

__global__ void prep_w_kernel(const float* __restrict__ W1) {
    int idx = blockIdx.x * blockDim.x + threadIdx.x;
    if (idx >= HID * 200) return;
    int row = idx / 200;
    int kg  = idx - row * 200;
    uchar4 v = make_uchar4(0, 0, 0, 0);
    if (kg < INF / 4) {
        float4 w4 = *(const float4*)(W1 + (size_t)row * INF + kg * 4);
        float ws[4] = {w4.x, w4.y, w4.z, w4.w};
        unsigned char s[4];
#pragma unroll
        for (int i = 0; i < 4; i++) {
            float w = ws[i];
            s[i] = (unsigned char)(signed char)((w > 0.0f) ? 1 : ((w < 0.0f) ? -1 : 0));
        }
        v = make_uchar4(s[0], s[1], s[2], s[3]);
    }
    *(uchar4*)(g_Sq + (size_t)row * KSB + kg * 4) = v;
}

__global__ void init_out_kernel(const float* __restrict__ b2, float* __restrict__ out) {
    int i = blockIdx.x * blockDim.x + threadIdx.x;
    if (i < BATCH * OUTF) out[i] = b2[i % OUTF];
}

// -------------------- GEMM1 + fused FC2 --------------------
__device__ __forceinline__ void load_chunk(uint32_t sbase, int stage, int kc,
                                           int m0, int n0, int tid) {
    uint32_t sa = sbase + stage * STAGE_BYTES;
    uint32_t sb = sa + A_BYTES;
    const signed char* gA = g_Xq + (size_t)m0 * KXB + (size_t)kc * 128;
#pragma unroll
    for (int i = 0; i < 8; i++) {                 // A: 128 rows x 8 x 16B, 128 threads
        int id = i * 128 + tid;
        int r = id >> 3, s = id & 7;
        cp16(sa + swz128((uint32_t)(r * 128 + s * 16)), gA + (size_t)r * KXB + s * 16);
    }
#pragma unroll
    for (int i = 0; i < 4; i++) {                 // B: 64 rows; source wraps mod 800 per 16B
        int id = i * 128 + tid;
        int r = id >> 3, s = id & 7;
        int g = kc * 128 + s * 16;
        int bsrc = (g >= 1600) ? (g - 1600) : ((g >= 800) ? (g - 800) : g);
        cp16(sb + swz128((uint32_t)(r * 128 + s * 16)),
             g_Sq + (size_t)(n0 + r) * KSB + bsrc);
    }
}

__global__ void __launch_bounds__(128, 3) gemm1_kernel(const float* __restrict__ b1,
                                                       const float* __restrict__ W2,
                                                       float* __restrict__ out) {
    extern __shared__ char dsm[];
    const int tid  = threadIdx.x;
    const int lane = tid & 31;
    const int wid  = tid >> 5;
    const int wm   = wid & 1;        // M offset wm*64
    const int wn   = (wid >> 1) & 1; // N offset wn*32
    const int m0 = blockIdx.x * BM;
    const int n0 = blockIdx.y * BN;
    const uint32_t sbase = smem_u32(dsm);

    // per-thread ldmatrix base byte offsets (pre-swizzle); same formulas as validated R7/R10
    const uint32_t aoff0 = (uint32_t)((wm * 64 + (lane & 15)) * 128 + (lane >> 4) * 16);
    const uint32_t boff0 = (uint32_t)((wn * 32 + (lane & 7) + ((lane >> 4) << 3)) * 128
                                      + ((lane >> 3) & 1) * 16);

    int acc[4][4][4];
#pragma unroll
    for (int mf = 0; mf < 4; mf++)
#pragma unroll
        for (int nf = 0; nf < 4; nf++)
#pragma unroll
            for (int i = 0; i < 4; i++) acc[mf][nf][i] = 0;

    // prologue
    load_chunk(sbase, 0, 0, m0, n0, tid); cp_commit();
    load_chunk(sbase, 1, 1, m0, n0, tid); cp_commit();

    int stage = 0;
    for (int j = 0; j < NCH; j++) {
        asm volatile("cp.async.wait_group 1;\n" ::: "memory");
        __syncthreads();

        uint32_t sa = sbase + stage * STAGE_BYTES;
        uint32_t sb = sa + A_BYTES;
        uint32_t af[2][4][4];
        uint32_t bf[2][4][2];
        // preload kk=0 fragments FIRST (ldsm latency overlaps cp.async issue below)
#pragma unroll
        for (int mf = 0; mf < 4; mf++)
            ldsm_x4(af[0][mf][0], af[0][mf][1], af[0][mf][2], af[0][mf][3],
                    sa + swz128(aoff0 + (uint32_t)(mf * 2048)));
        {
            uint32_t r0, r1, r2, r3;
            ldsm_x4(r0, r1, r2, r3, sb + swz128(boff0));
            bf[0][0][0] = r0;  bf[0][0][1] = r1;
            bf[0][1][0] = r2;  bf[0][1][1] = r3;
            ldsm_x4(r0, r1, r2, r3, sb + swz128(boff0 + 2048u));
            bf[0][2][0] = r0;  bf[0][2][1] = r1;
            bf[0][3][0] = r2;  bf[0][3][1] = r3;
        }

        int jn = j + 2;
        if (jn < NCH) {
            int sn = stage + 2; if (sn >= STAGES) sn -= STAGES;
            load_chunk(sbase, sn, jn, m0, n0, tid);
        }
        cp_commit();

#pragma unroll
        for (int kk = 0; kk < 4; kk++) {
            const int cur = kk & 1, nxt = cur ^ 1;
            if (j == 12 && kk >= 2) break;   // steps 50,51 are zero pad: exact skip
            // limb boundary before k32-step 25: acc *= 254 (= 4064/16, exact in s32)
            if (kk == 1 && j == 6) {
#pragma unroll
                for (int mf = 0; mf < 4; mf++)
#pragma unroll
                    for (int nf = 0; nf < 4; nf++)
#pragma unroll
                        for (int i = 0; i < 4; i++) acc[mf][nf][i] *= 254;
            }
            if (kk < 3 && !(j == 12 && kk == 1)) {   // prefetch kk+1 frags while issuing IMMAs
#pragma unroll
                for (int mf = 0; mf < 4; mf++)
                    ldsm_x4(af[nxt][mf][0], af[nxt][mf][1], af[nxt][mf][2], af[nxt][mf][3],
                            sa + swz128(aoff0 + (uint32_t)(mf * 2048 + (kk + 1) * 32)));
                uint32_t r0, r1, r2, r3;
                ldsm_x4(r0, r1, r2, r3, sb + swz128(boff0 + (uint32_t)((kk + 1) * 32)));
                bf[nxt][0][0] = r0;  bf[nxt][0][1] = r1;
                bf[nxt][1][0] = r2;  bf[nxt][1][1] = r3;
                ldsm_x4(r0, r1, r2, r3, sb + swz128(boff0 + (uint32_t)(2048 + (kk + 1) * 32)));
                bf[nxt][2][0] = r0;  bf[nxt][2][1] = r1;
                bf[nxt][3][0] = r2;  bf[nxt][3][1] = r3;
            }
#pragma unroll
            for (int mf = 0; mf < 4; mf++)
#pragma unroll
                for (int nf = 0; nf < 4; nf++)
                    imma16832(acc[mf][nf], af[cur][mf][0], af[cur][mf][1],
                              af[cur][mf][2], af[cur][mf][3],
                              bf[cur][nf][0], bf[cur][nf][1]);
        }
        stage++; if (stage >= STAGES) stage = 0;
    }

    // ---- epilogue: h tile -> smem (clip(acc/4064 + b1)), then fused fc2 partial ----
    __syncthreads();   // everyone done reading stage smem before overwrite
    float* hs = (float*)dsm;
    const float SCL = (float)(1.0 / 4064.0);
    const int rloc0 = wm * 64 + (lane >> 2);
    const int cloc0 = wn * 32 + (lane & 3) * 2;
#pragma unroll
    for (int mf = 0; mf < 4; mf++) {
#pragma unroll
        for (int nf = 0; nf < 4; nf++) {
            int cl = cloc0 + nf * 8;
            float bb0 = __ldg(b1 + n0 + cl), bb1 = __ldg(b1 + n0 + cl + 1);
#pragma unroll
            for (int half = 0; half < 2; half++) {
                int rl = rloc0 + mf * 16 + half * 8;
                float v0 = fmaf((float)acc[mf][nf][2 * half],     SCL, bb0);
                float v1 = fmaf((float)acc[mf][nf][2 * half + 1], SCL, bb1);
                v0 = fminf(1.0f, fmaxf(-1.0f, v0));
                v1 = fminf(1.0f, fmaxf(-1.0f, v1));
                *(float2*)(hs + rl * HS + cl) = make_float2(v0, v1);
            }
        }
    }
    __syncthreads();

    // fc2 partial: thread t owns row t, 64 cols; W2 loads warp-uniform (L1-resident)
    {
        float accf[OUTF];
#pragma unroll
        for (int o = 0; o < OUTF; o++) accf[o] = 0.0f;
        const float4* hv4 = (const float4*)(hs + tid * HS);
        const float4* W2v = (const float4*)W2;
        const int base = n0 >> 2;
#pragma unroll 4
        for (int c4 = 0; c4 < 16; c4++) {
            float4 h4 = hv4[c4];
#pragma unroll
            for (int o = 0; o < OUTF; o++) {
                float4 w = __ldg(&W2v[o * (HID / 4) + base + c4]);
                accf[o] += h4.x * w.x + h4.y * w.y + h4.z * w.z + h4.w * w.w;
            }
        }
        float* op = out + (size_t)(m0 + tid) * OUTF;
#pragma unroll
        for (int o = 0; o < OUTF; o++) atomicAdd(op + o, accf[o]);
    }
}

// -------------------- launch --------------------
extern "C" void kernel_launch(void* const* d_in, const int* in_sizes, int n_in,
                              void* d_out, int out_size) {
    const float* x  = (const float*)d_in[0];
    const float* W1 = (const float*)d_in[1];
    const float* b1 = (const float*)d_in[2];
    const float* W2 = (const float*)d_in[3];
    const float* b2 = (const float*)d_in[4];
    float* out = (float*)d_out;

    cudaFuncSetAttribute(gemm1_kernel, cudaFuncAttributeMaxDynamicSharedMemorySize, SMEM_TOTAL);

    init_out_kernel<<<(BATCH * OUTF + 255) / 256, 256>>>(b2, out);
    prep_x_kernel<<<(BATCH * 216 + 255) / 256, 256>>>(x);
    prep_w_kernel<<<(HID * 200 + 255) / 256, 256>>>(W1);
    gemm1_kernel<<<dim3(BATCH / BM, HID / BN), 128, SMEM_TOTAL>>>(b1, W2, out);
}